// round 1
// baseline (speedup 1.0000x reference)
#include <cuda_runtime.h>
#include <math.h>

// ---------------------------------------------------------------------------
// Problem constants
// ---------------------------------------------------------------------------
#define U_   40000
#define I_   30000
#define N_   70000
#define DL   128
#define DX   64
#define SLOPE 0.01f
#define EPS_N 1e-12f

// ---------------------------------------------------------------------------
// Scratch: one big static device buffer, addressed by constexpr offsets.
// ---------------------------------------------------------------------------
// layout (floats):
//   tfeat : I*DL
//   x     : N*DL
//   y     : N*DL      (conv messages / reused)
//   h     : N*DL      (aggregation)
//   t1    : N*DX
//   t2    : N*DX
//   xs    : N*DX      (x after layer 1)
//   reps  : 3*N*DX
static const long long OFF_TFEAT = 0;
static const long long OFF_X     = OFF_TFEAT + (long long)I_ * DL;
static const long long OFF_Y     = OFF_X     + (long long)N_ * DL;
static const long long OFF_H     = OFF_Y     + (long long)N_ * DL;
static const long long OFF_T1    = OFF_H     + (long long)N_ * DL;
static const long long OFF_T2    = OFF_T1    + (long long)N_ * DX;
static const long long OFF_XS    = OFF_T2    + (long long)N_ * DX;
static const long long OFF_REPS  = OFF_XS    + (long long)N_ * DX;
static const long long BUF_FLOATS = OFF_REPS + 3LL * N_ * DX;

__device__ float g_buf[BUF_FLOATS];

__device__ __forceinline__ float lrelu(float v) { return v >= 0.f ? v : SLOPE * v; }

// ---------------------------------------------------------------------------
// t_feat = scatter_mean(word_emb[word_ids], item_ids)  — item_ids is sorted,
// so each item's words are a contiguous range: binary search, no atomics.
// One block (128 threads) per item; thread f accumulates feature f.
// ---------------------------------------------------------------------------
__global__ void tfeat_kernel(const int* __restrict__ item_ids,
                             const int* __restrict__ word_ids,
                             const float* __restrict__ word_emb, int words) {
    int item = blockIdx.x;
    // lower_bound(item)
    int lo = 0, hi = words;
    while (lo < hi) { int mid = (lo + hi) >> 1; if (item_ids[mid] < item) lo = mid + 1; else hi = mid; }
    int start = lo;
    // lower_bound(item+1)
    hi = words;
    while (lo < hi) { int mid = (lo + hi) >> 1; if (item_ids[mid] < item + 1) lo = mid + 1; else hi = mid; }
    int end = lo;

    int f = threadIdx.x;
    float acc = 0.f;
    for (int w = start; w < end; w++)
        acc += word_emb[(size_t)word_ids[w] * DL + f];
    float cnt = (float)(end - start);
    g_buf[OFF_TFEAT + (size_t)item * DL + f] = acc / fmaxf(cnt, 1.f);
}

// ---------------------------------------------------------------------------
// Generic fp32 GEMM:  C[M x NCfull] = A[M x K] * op(B)  (+ bias)
//   TRANSB=true : B is (NCfull x K) row-major, C = A * B^T
//   TRANSB=false: B is (K x NCfull) row-major, C = A * B
// A may be external (Aext != nullptr) or internal (g_buf + Aoff).
// C is always internal (g_buf + Coff). A row stride == K, C row stride == NCfull.
// Tile: 32 rows x 64 cols per block, 256 threads, K chunked by 64.
// Each thread: 4 rows x 2 cols (cols lane and lane+32 -> conflict-free sW).
// ---------------------------------------------------------------------------
template <int K, bool TRANSB>
__global__ void gemm_kernel(const float* __restrict__ Aext, long long Aoff,
                            const float* __restrict__ B,
                            const float* __restrict__ bias,
                            long long Coff, int M, int NCfull) {
    __shared__ float sW[64 * 64];
    __shared__ float sA[32 * 64];

    const float* A = Aext ? Aext : (const float*)(g_buf + Aoff);
    float* C = g_buf + Coff;

    int row0 = blockIdx.x * 32;
    int colBase = blockIdx.y * 64;
    int tid = threadIdx.x;
    int lane = tid & 31;
    int rg = tid >> 5;  // 0..7, 4 rows each

    float acc[4][2] = {{0.f, 0.f}, {0.f, 0.f}, {0.f, 0.f}, {0.f, 0.f}};

    for (int kt = 0; kt < K; kt += 64) {
        __syncthreads();
        // load 64x64 weight slice
        for (int i = tid; i < 64 * 64; i += 256) {
            int k = i >> 6, c = i & 63;
            float w;
            if (TRANSB) w = B[(size_t)(colBase + c) * K + (kt + k)];
            else        w = B[(size_t)(kt + k) * NCfull + colBase + c];
            sW[i] = w;
        }
        // load 32xK-chunk of A
        for (int i = tid; i < 32 * 64; i += 256) {
            int r = i >> 6, k = i & 63;
            int row = row0 + r;
            sA[i] = (row < M) ? A[(size_t)row * K + (kt + k)] : 0.f;
        }
        __syncthreads();

#pragma unroll 16
        for (int k = 0; k < 64; k++) {
            float w0 = sW[k * 64 + lane];
            float w1 = sW[k * 64 + lane + 32];
#pragma unroll
            for (int r = 0; r < 4; r++) {
                float a = sA[(rg * 4 + r) * 64 + k];
                acc[r][0] += a * w0;
                acc[r][1] += a * w1;
            }
        }
    }

    float b0 = bias ? bias[colBase + lane]      : 0.f;
    float b1 = bias ? bias[colBase + lane + 32] : 0.f;
#pragma unroll
    for (int r = 0; r < 4; r++) {
        int row = row0 + rg * 4 + r;
        if (row < M) {
            C[(size_t)row * NCfull + colBase + lane]      = acc[r][0] + b0;
            C[(size_t)row * NCfull + colBase + lane + 32] = acc[r][1] + b1;
        }
    }
}

// ---------------------------------------------------------------------------
// Row-normalize x (N x 128). Rows < U come from pref (copy+normalize),
// rows >= U were already written into g_buf[OFF_X] by the MLP GEMM.
// One warp per row, float4 per lane.
// ---------------------------------------------------------------------------
__global__ void normalize_kernel(const float* __restrict__ pref_m) {
    int warp = threadIdx.x >> 5, lane = threadIdx.x & 31;
    int row = blockIdx.x * 8 + warp;
    if (row >= N_) return;
    const float* s = (row < U_) ? (pref_m + (size_t)row * DL)
                                : (const float*)(g_buf + OFF_X + (size_t)row * DL);
    float4 v = ((const float4*)s)[lane];
    float ss = v.x * v.x + v.y * v.y + v.z * v.z + v.w * v.w;
#pragma unroll
    for (int o = 16; o; o >>= 1) ss += __shfl_xor_sync(0xffffffffu, ss, o);
    float inv = 1.f / fmaxf(sqrtf(ss), EPS_N);
    v.x *= inv; v.y *= inv; v.z *= inv; v.w *= inv;
    ((float4*)(g_buf + OFF_X + (size_t)row * DL))[lane] = v;
}

// ---------------------------------------------------------------------------
// Simple fills / activations
// ---------------------------------------------------------------------------
__global__ void zero_kernel(long long off, int n) {
    int i = blockIdx.x * blockDim.x + threadIdx.x;
    if (i < n) g_buf[off + i] = 0.f;
}

__global__ void lrelu_kernel(long long off, int n) {
    int i = blockIdx.x * blockDim.x + threadIdx.x;
    if (i < n) g_buf[off + i] = lrelu(g_buf[off + i]);
}

// ---------------------------------------------------------------------------
// Edge scatter: h[dst] += y[src]  (atomic).  One thread per 4 features.
// ---------------------------------------------------------------------------
template <int K>
__global__ void scatter_kernel(const int* __restrict__ src, const int* __restrict__ dst,
                               long long yoff, long long hoff, int E) {
    const int PE = K / 4;
    long long t = (long long)blockIdx.x * blockDim.x + threadIdx.x;
    int e = (int)(t / PE);
    if (e >= E) return;
    int j = (int)(t % PE);
    int s = src[e], d = dst[e];
    const float4 v = *(const float4*)(g_buf + yoff + (size_t)s * K + j * 4);
    float* hp = g_buf + hoff + (size_t)d * K + j * 4;
    atomicAdd(hp + 0, v.x);
    atomicAdd(hp + 1, v.y);
    atomicAdd(hp + 2, v.z);
    atomicAdd(hp + 3, v.w);
}

// ---------------------------------------------------------------------------
// x_new = lrelu( t1 + lrelu(t2) + id_emb )     (all N x 64)
// t1 = h @ gW^T + g_b (bias already in), t2 = x @ linW^T + lin_b
// ---------------------------------------------------------------------------
__global__ void combine_kernel(const float* __restrict__ id_emb, long long outOff) {
    int i = blockIdx.x * blockDim.x + threadIdx.x;
    if (i >= N_ * DX) return;
    float v = g_buf[OFF_T1 + i] + lrelu(g_buf[OFF_T2 + i]) + id_emb[i];
    g_buf[outOff + i] = lrelu(v);
}

// ---------------------------------------------------------------------------
// Final scoring.  One warp per batch element; 2 features per lane.
// out: [pos_scores | neg_scores | pre_pos | pre_neg], each length Bn.
// ---------------------------------------------------------------------------
__global__ void score_kernel(const int* __restrict__ un, const int* __restrict__ pn,
                             const int* __restrict__ nn, float* __restrict__ out, int Bn) {
    int warp = threadIdx.x >> 5, lane = threadIdx.x & 31;
    int b = blockIdx.x * 8 + warp;
    if (b >= Bn) return;
    int iu = un[b], ip = pn[b], ig = nn[b];
    const float* r0 = g_buf + OFF_REPS;
    const float* r1 = g_buf + OFF_REPS + (size_t)N_ * DX;
    const float* r2 = g_buf + OFF_REPS + 2 * (size_t)N_ * DX;

    float2 u0 = ((const float2*)(r0 + (size_t)iu * DX))[lane];
    float2 u1 = ((const float2*)(r1 + (size_t)iu * DX))[lane];
    float2 u2 = ((const float2*)(r2 + (size_t)iu * DX))[lane];
    float2 p0 = ((const float2*)(r0 + (size_t)ip * DX))[lane];
    float2 p1 = ((const float2*)(r1 + (size_t)ip * DX))[lane];
    float2 p2 = ((const float2*)(r2 + (size_t)ip * DX))[lane];
    float2 n0 = ((const float2*)(r0 + (size_t)ig * DX))[lane];
    float2 n1 = ((const float2*)(r1 + (size_t)ig * DX))[lane];
    float2 n2 = ((const float2*)(r2 + (size_t)ig * DX))[lane];

    const float third = 1.f / 3.f;
    float pux = (u0.x + u1.x + u2.x) * third, puy = (u0.y + u1.y + u2.y) * third;
    float ppx = (p0.x + p1.x + p2.x) * third, ppy = (p0.y + p1.y + p2.y) * third;
    float pnx = (n0.x + n1.x + n2.x) * third, pny = (n0.y + n1.y + n2.y) * third;

    float prepos  = u2.x * p2.x + u2.y * p2.y;
    float preneg  = u2.x * n2.x + u2.y * n2.y;
    float postpos = pux * ppx + puy * ppy;
    float postneg = pux * pnx + puy * pny;

#pragma unroll
    for (int o = 16; o; o >>= 1) {
        prepos  += __shfl_xor_sync(0xffffffffu, prepos, o);
        preneg  += __shfl_xor_sync(0xffffffffu, preneg, o);
        postpos += __shfl_xor_sync(0xffffffffu, postpos, o);
        postneg += __shfl_xor_sync(0xffffffffu, postneg, o);
    }
    if (lane == 0) {
        out[b]          = postpos * (1.f / (1.f + expf(-prepos)));
        out[Bn + b]     = postneg * (1.f / (1.f + expf(-preneg)));
        out[2 * Bn + b] = prepos;
        out[3 * Bn + b] = preneg;
    }
}

// ---------------------------------------------------------------------------
// Host launcher — kernel launches only, graph-capturable.
// ---------------------------------------------------------------------------
extern "C" void kernel_launch(void* const* d_in, const int* in_sizes, int n_in,
                              void* d_out, int out_size) {
    const float* v_feat   = (const float*)d_in[0];
    const float* a_feat   = (const float*)d_in[1];
    const float* word_emb = (const float*)d_in[2];
    const float* id_emb   = (const float*)d_in[3];
    const float* pref     = (const float*)d_in[4];
    const float* mlp_w    = (const float*)d_in[5];
    const float* mlp_b    = (const float*)d_in[6];
    const float* c1w      = (const float*)d_in[7];
    const float* l1w      = (const float*)d_in[8];
    const float* l1b      = (const float*)d_in[9];
    const float* g1w      = (const float*)d_in[10];
    const float* g1b      = (const float*)d_in[11];
    const float* c2w      = (const float*)d_in[12];
    const float* l2w      = (const float*)d_in[13];
    const float* l2b      = (const float*)d_in[14];
    const float* g2w      = (const float*)d_in[15];
    const float* g2b      = (const float*)d_in[16];
    const int*   edge     = (const int*)d_in[17];
    const int*   words    = (const int*)d_in[18];
    const int*   un       = (const int*)d_in[19];
    const int*   pn       = (const int*)d_in[20];
    const int*   nn       = (const int*)d_in[21];

    int E  = in_sizes[17] / 2;
    int W  = in_sizes[18] / 2;
    int Bn = in_sizes[19];
    const int* src = edge;
    const int* dst = edge + E;
    const int* item_ids = words;
    const int* word_ids = words + W;

    // t_feat (shared by modality 2)
    tfeat_kernel<<<I_, 128>>>(item_ids, word_ids, word_emb, W);

    for (int m = 0; m < 3; m++) {
        const float* feat = (m == 0) ? v_feat : (m == 1) ? a_feat : nullptr;
        long long featOff = OFF_TFEAT;  // used only when feat==nullptr (m==2)

        // 1) item MLP: x[U: ] = feat @ mlp_w^T + mlp_b   (I x 128)
        {
            dim3 grid((I_ + 31) / 32, 2);
            gemm_kernel<128, true><<<grid, 256>>>(feat, featOff,
                                                  mlp_w + (size_t)m * DL * DL,
                                                  mlp_b + (size_t)m * DL,
                                                  OFF_X + (long long)U_ * DL, I_, DL);
        }
        // 2) copy pref rows + row-normalize all N rows
        normalize_kernel<<<(N_ + 7) / 8, 256>>>(pref + (size_t)m * U_ * DL);

        // ---- layer 1 (128 -> 64) ----
        // y = x @ c1   (N x 128)
        {
            dim3 grid((N_ + 31) / 32, 2);
            gemm_kernel<128, false><<<grid, 256>>>(nullptr, OFF_X,
                                                   c1w + (size_t)m * DL * DL, nullptr,
                                                   OFF_Y, N_, DL);
        }
        // h = segment_sum(y[src], dst); lrelu
        zero_kernel<<<(N_ * DL + 255) / 256, 256>>>(OFF_H, N_ * DL);
        {
            long long tt = (long long)E * (DL / 4);
            scatter_kernel<128><<<(unsigned)((tt + 255) / 256), 256>>>(src, dst, OFF_Y, OFF_H, E);
        }
        lrelu_kernel<<<(N_ * DL + 255) / 256, 256>>>(OFF_H, N_ * DL);
        // t1 = h @ g1^T + g1b ; t2 = x @ l1^T + l1b   (N x 64)
        {
            dim3 grid((N_ + 31) / 32, 1);
            gemm_kernel<128, true><<<grid, 256>>>(nullptr, OFF_H,
                                                  g1w + (size_t)m * DX * DL,
                                                  g1b + (size_t)m * DX, OFF_T1, N_, DX);
            gemm_kernel<128, true><<<grid, 256>>>(nullptr, OFF_X,
                                                  l1w + (size_t)m * DX * DL,
                                                  l1b + (size_t)m * DX, OFF_T2, N_, DX);
        }
        // xs = lrelu(t1 + lrelu(t2) + id_emb)
        combine_kernel<<<(N_ * DX + 255) / 256, 256>>>(id_emb, OFF_XS);

        // ---- layer 2 (64 -> 64) ----
        {
            dim3 grid((N_ + 31) / 32, 1);
            gemm_kernel<64, false><<<grid, 256>>>(nullptr, OFF_XS,
                                                  c2w + (size_t)m * DX * DX, nullptr,
                                                  OFF_Y, N_, DX);
        }
        zero_kernel<<<(N_ * DX + 255) / 256, 256>>>(OFF_H, N_ * DX);
        {
            long long tt = (long long)E * (DX / 4);
            scatter_kernel<64><<<(unsigned)((tt + 255) / 256), 256>>>(src, dst, OFF_Y, OFF_H, E);
        }
        lrelu_kernel<<<(N_ * DX + 255) / 256, 256>>>(OFF_H, N_ * DX);
        {
            dim3 grid((N_ + 31) / 32, 1);
            gemm_kernel<64, true><<<grid, 256>>>(nullptr, OFF_H,
                                                 g2w + (size_t)m * DX * DX,
                                                 g2b + (size_t)m * DX, OFF_T1, N_, DX);
            gemm_kernel<64, true><<<grid, 256>>>(nullptr, OFF_XS,
                                                 l2w + (size_t)m * DX * DX,
                                                 l2b + (size_t)m * DX, OFF_T2, N_, DX);
        }
        combine_kernel<<<(N_ * DX + 255) / 256, 256>>>(id_emb, OFF_REPS + (long long)m * N_ * DX);
    }

    score_kernel<<<(Bn + 7) / 8, 256>>>(un, pn, nn, (float*)d_out, Bn);
}

// round 2
// speedup vs baseline: 2.2153x; 2.2153x over previous
#include <cuda_runtime.h>
#include <math.h>

// ---------------------------------------------------------------------------
// Problem constants
// ---------------------------------------------------------------------------
#define U_   40000
#define I_   30000
#define N_   70000
#define DL   128
#define DX   64
#define SLOPE 0.01f
#define EPS_N 1e-12f
#define E_MAX 520000

// ---------------------------------------------------------------------------
// Scratch buffers (static device globals; no allocation anywhere)
// ---------------------------------------------------------------------------
static const long long OFF_TFEAT = 0;
static const long long OFF_X     = OFF_TFEAT + (long long)I_ * DL;
static const long long OFF_Y     = OFF_X     + (long long)N_ * DL;
static const long long OFF_H     = OFF_Y     + (long long)N_ * DL;
static const long long OFF_T2    = OFF_H     + (long long)N_ * DL;
static const long long OFF_XS    = OFF_T2    + (long long)N_ * DX;
static const long long OFF_REPS  = OFF_XS    + (long long)N_ * DX;
static const long long BUF_FLOATS = OFF_REPS + 3LL * N_ * DX;

__device__ float g_buf[BUF_FLOATS];

__device__ int g_rowstart[N_ + 1];
__device__ int g_cursor[N_];          // counts, then fill cursor
__device__ int g_csr[E_MAX];
__device__ int g_blocksums[512];

__device__ __forceinline__ float lrelu(float v) { return v >= 0.f ? v : SLOPE * v; }

// ---------------------------------------------------------------------------
// t_feat = scatter_mean(word_emb[word_ids], item_ids); item_ids sorted.
// ---------------------------------------------------------------------------
__global__ void tfeat_kernel(const int* __restrict__ item_ids,
                             const int* __restrict__ word_ids,
                             const float* __restrict__ word_emb, int words) {
    int item = blockIdx.x;
    int lo = 0, hi = words;
    while (lo < hi) { int mid = (lo + hi) >> 1; if (item_ids[mid] < item) lo = mid + 1; else hi = mid; }
    int start = lo;
    hi = words;
    while (lo < hi) { int mid = (lo + hi) >> 1; if (item_ids[mid] < item + 1) lo = mid + 1; else hi = mid; }
    int end = lo;

    int f = threadIdx.x;
    float acc = 0.f;
    for (int w = start; w < end; w++)
        acc += word_emb[(size_t)word_ids[w] * DL + f];
    float cnt = (float)(end - start);
    g_buf[OFF_TFEAT + (size_t)item * DL + f] = acc / fmaxf(cnt, 1.f);
}

// ---------------------------------------------------------------------------
// CSR build: counting sort of edges by dst.
// ---------------------------------------------------------------------------
__global__ void zero_int_kernel(int n) {
    int i = blockIdx.x * blockDim.x + threadIdx.x;
    if (i < n) g_cursor[i] = 0;
}
__global__ void hist_kernel(const int* __restrict__ dst, int E) {
    int e = blockIdx.x * blockDim.x + threadIdx.x;
    if (e < E) atomicAdd(&g_cursor[dst[e]], 1);
}
#define SCAN_B 512
__global__ void scan1_kernel(int n) {
    __shared__ int sh[SCAN_B];
    int t = threadIdx.x, i = blockIdx.x * SCAN_B + t;
    int v = (i < n) ? g_cursor[i] : 0;
    sh[t] = v; __syncthreads();
    for (int o = 1; o < SCAN_B; o <<= 1) {
        int tv = (t >= o) ? sh[t - o] : 0;
        __syncthreads();
        sh[t] += tv;
        __syncthreads();
    }
    if (i < n) g_rowstart[i] = sh[t] - v;  // exclusive
    if (t == SCAN_B - 1) g_blocksums[blockIdx.x] = sh[t];
}
__global__ void scan2_kernel(int nb) {
    __shared__ int sh[SCAN_B];
    int t = threadIdx.x;
    int v = (t < nb) ? g_blocksums[t] : 0;
    sh[t] = v; __syncthreads();
    for (int o = 1; o < SCAN_B; o <<= 1) {
        int tv = (t >= o) ? sh[t - o] : 0;
        __syncthreads();
        sh[t] += tv;
        __syncthreads();
    }
    if (t < nb) g_blocksums[t] = sh[t] - v;  // exclusive
}
__global__ void scan3_kernel(int n, int E) {
    int i = blockIdx.x * blockDim.x + threadIdx.x;
    if (i < n) g_rowstart[i] += g_blocksums[i / SCAN_B];
    if (i == 0) g_rowstart[n] = E;
}
__global__ void fill_kernel(const int* __restrict__ src, const int* __restrict__ dst, int E) {
    int e = blockIdx.x * blockDim.x + threadIdx.x;
    if (e < E) {
        int d = dst[e];
        int p = g_rowstart[d] + atomicAdd(&g_cursor[d], 1);
        g_csr[p] = src[e];
    }
}

// ---------------------------------------------------------------------------
// Atomic-free aggregation: h[row] = sum over neighbors y[nbr].
// One warp per (row, 32-feature chunk).
// ---------------------------------------------------------------------------
template <int K>
__global__ void gather_kernel(long long yoff, long long hoff) {
    const int CH = K / 32;
    int gw = blockIdx.x * (blockDim.x >> 5) + (threadIdx.x >> 5);
    int row = gw / CH, ch = gw % CH;
    if (row >= N_) return;
    int lane = threadIdx.x & 31;
    int s = g_rowstart[row], e = g_rowstart[row + 1];
    float acc = 0.f;
    const float* y = g_buf + yoff + ch * 32 + lane;
    for (int i = s; i < e; i++) {
        int nbr = g_csr[i];
        acc += y[(size_t)nbr * K];
    }
    g_buf[hoff + (size_t)row * K + ch * 32 + lane] = acc;
}

// ---------------------------------------------------------------------------
// GEMM: C[M x NC] = op(A) * op(B) (+bias) (+combine epilogue)
//   BM=128, BN=64, BK=32, 256 threads, 8x4 per-thread tile.
//   TRANSB : B is (NC x K) row-major -> C = A*B^T ; else B is (K x NC).
//   LRELU_A: apply lrelu to A elements on load.
//   COMBINE: out = lrelu(acc + bias + lrelu(t2[row]) + id_emb[row]) (NC==64).
// ---------------------------------------------------------------------------
#define BM 128
#define BN 64
#define BK 32
#define SAS (BM + 4)   // padded strides
#define SBS (BN + 4)

template <int K, bool TRANSB, bool LRELU_A, bool COMBINE>
__global__ void __launch_bounds__(256)
gemm_kernel(const float* __restrict__ Aext, long long Aoff,
            const float* __restrict__ B, const float* __restrict__ bias,
            long long t2off, const float* __restrict__ id_emb,
            long long Coff, int M, int NC) {
    __shared__ float sA[BK * SAS];
    __shared__ float sB[BK * SBS];

    const float* A = Aext ? Aext : (const float*)(g_buf + Aoff);
    float* C = g_buf + Coff;

    int row0 = blockIdx.x * BM;
    int colBase = blockIdx.y * BN;
    int tid = threadIdx.x;
    int tm8 = (tid >> 4) << 3;   // 0,8,...,120
    int tn4 = (tid & 15) << 2;   // 0,4,...,60

    float4 acc[8];
#pragma unroll
    for (int r = 0; r < 8; r++) acc[r] = make_float4(0.f, 0.f, 0.f, 0.f);

    for (int kt = 0; kt < K; kt += BK) {
        __syncthreads();
        // Load A tile (BM x BK), store transposed sA[k][m]
#pragma unroll
        for (int i = tid; i < (BM * BK) / 4; i += 256) {
            int r = i >> 3;
            int k4 = (i & 7) << 2;
            int row = row0 + r;
            float4 v = make_float4(0.f, 0.f, 0.f, 0.f);
            if (row < M) v = *(const float4*)&A[(size_t)row * K + kt + k4];
            if (LRELU_A) {
                v.x = lrelu(v.x); v.y = lrelu(v.y); v.z = lrelu(v.z); v.w = lrelu(v.w);
            }
            sA[(k4 + 0) * SAS + r] = v.x;
            sA[(k4 + 1) * SAS + r] = v.y;
            sA[(k4 + 2) * SAS + r] = v.z;
            sA[(k4 + 3) * SAS + r] = v.w;
        }
        // Load B tile (BK x BN) as sB[k][n]
        if (TRANSB) {
#pragma unroll
            for (int i = tid; i < (BN * BK) / 4; i += 256) {
                int n = i >> 3;
                int k4 = (i & 7) << 2;
                float4 v = *(const float4*)&B[(size_t)(colBase + n) * K + kt + k4];
                sB[(k4 + 0) * SBS + n] = v.x;
                sB[(k4 + 1) * SBS + n] = v.y;
                sB[(k4 + 2) * SBS + n] = v.z;
                sB[(k4 + 3) * SBS + n] = v.w;
            }
        } else {
#pragma unroll
            for (int i = tid; i < (BN * BK) / 4; i += 256) {
                int k = i >> 4;
                int n4 = (i & 15) << 2;
                float4 v = *(const float4*)&B[(size_t)(kt + k) * NC + colBase + n4];
                *(float4*)&sB[k * SBS + n4] = v;
            }
        }
        __syncthreads();

#pragma unroll 8
        for (int k = 0; k < BK; k++) {
            float4 b  = *(float4*)&sB[k * SBS + tn4];
            float4 a0 = *(float4*)&sA[k * SAS + tm8];
            float4 a1 = *(float4*)&sA[k * SAS + tm8 + 4];
            acc[0].x += a0.x * b.x; acc[0].y += a0.x * b.y; acc[0].z += a0.x * b.z; acc[0].w += a0.x * b.w;
            acc[1].x += a0.y * b.x; acc[1].y += a0.y * b.y; acc[1].z += a0.y * b.z; acc[1].w += a0.y * b.w;
            acc[2].x += a0.z * b.x; acc[2].y += a0.z * b.y; acc[2].z += a0.z * b.z; acc[2].w += a0.z * b.w;
            acc[3].x += a0.w * b.x; acc[3].y += a0.w * b.y; acc[3].z += a0.w * b.z; acc[3].w += a0.w * b.w;
            acc[4].x += a1.x * b.x; acc[4].y += a1.x * b.y; acc[4].z += a1.x * b.z; acc[4].w += a1.x * b.w;
            acc[5].x += a1.y * b.x; acc[5].y += a1.y * b.y; acc[5].z += a1.y * b.z; acc[5].w += a1.y * b.w;
            acc[6].x += a1.z * b.x; acc[6].y += a1.z * b.y; acc[6].z += a1.z * b.z; acc[6].w += a1.z * b.w;
            acc[7].x += a1.w * b.x; acc[7].y += a1.w * b.y; acc[7].z += a1.w * b.z; acc[7].w += a1.w * b.w;
        }
    }

    float4 b4 = make_float4(0.f, 0.f, 0.f, 0.f);
    if (bias) b4 = *(const float4*)&bias[colBase + tn4];

#pragma unroll
    for (int r = 0; r < 8; r++) {
        int row = row0 + tm8 + r;
        if (row >= M) break;
        float4 o = acc[r];
        o.x += b4.x; o.y += b4.y; o.z += b4.z; o.w += b4.w;
        if (COMBINE) {
            float4 t2v = *(const float4*)&g_buf[t2off + (size_t)row * DX + tn4];
            float4 idv = *(const float4*)&id_emb[(size_t)row * DX + tn4];
            o.x = lrelu(o.x + lrelu(t2v.x) + idv.x);
            o.y = lrelu(o.y + lrelu(t2v.y) + idv.y);
            o.z = lrelu(o.z + lrelu(t2v.z) + idv.z);
            o.w = lrelu(o.w + lrelu(t2v.w) + idv.w);
        }
        *(float4*)&C[(size_t)row * NC + colBase + tn4] = o;
    }
}

// ---------------------------------------------------------------------------
// Row-normalize x (N x 128): rows < U from pref, rows >= U in-place in g_buf.
// ---------------------------------------------------------------------------
__global__ void normalize_kernel(const float* __restrict__ pref_m) {
    int warp = threadIdx.x >> 5, lane = threadIdx.x & 31;
    int row = blockIdx.x * 8 + warp;
    if (row >= N_) return;
    const float* s = (row < U_) ? (pref_m + (size_t)row * DL)
                                : (const float*)(g_buf + OFF_X + (size_t)row * DL);
    float4 v = ((const float4*)s)[lane];
    float ss = v.x * v.x + v.y * v.y + v.z * v.z + v.w * v.w;
#pragma unroll
    for (int o = 16; o; o >>= 1) ss += __shfl_xor_sync(0xffffffffu, ss, o);
    float inv = 1.f / fmaxf(sqrtf(ss), EPS_N);
    v.x *= inv; v.y *= inv; v.z *= inv; v.w *= inv;
    ((float4*)(g_buf + OFF_X + (size_t)row * DL))[lane] = v;
}

// ---------------------------------------------------------------------------
// Final scoring. One warp per batch element; 2 features per lane.
// ---------------------------------------------------------------------------
__global__ void score_kernel(const int* __restrict__ un, const int* __restrict__ pn,
                             const int* __restrict__ nn, float* __restrict__ out, int Bn) {
    int warp = threadIdx.x >> 5, lane = threadIdx.x & 31;
    int b = blockIdx.x * 8 + warp;
    if (b >= Bn) return;
    int iu = un[b], ip = pn[b], ig = nn[b];
    const float* r0 = g_buf + OFF_REPS;
    const float* r1 = g_buf + OFF_REPS + (size_t)N_ * DX;
    const float* r2 = g_buf + OFF_REPS + 2 * (size_t)N_ * DX;

    float2 u0 = ((const float2*)(r0 + (size_t)iu * DX))[lane];
    float2 u1 = ((const float2*)(r1 + (size_t)iu * DX))[lane];
    float2 u2 = ((const float2*)(r2 + (size_t)iu * DX))[lane];
    float2 p0 = ((const float2*)(r0 + (size_t)ip * DX))[lane];
    float2 p1 = ((const float2*)(r1 + (size_t)ip * DX))[lane];
    float2 p2 = ((const float2*)(r2 + (size_t)ip * DX))[lane];
    float2 n0 = ((const float2*)(r0 + (size_t)ig * DX))[lane];
    float2 n1 = ((const float2*)(r1 + (size_t)ig * DX))[lane];
    float2 n2 = ((const float2*)(r2 + (size_t)ig * DX))[lane];

    const float third = 1.f / 3.f;
    float pux = (u0.x + u1.x + u2.x) * third, puy = (u0.y + u1.y + u2.y) * third;
    float ppx = (p0.x + p1.x + p2.x) * third, ppy = (p0.y + p1.y + p2.y) * third;
    float pnx = (n0.x + n1.x + n2.x) * third, pny = (n0.y + n1.y + n2.y) * third;

    float prepos  = u2.x * p2.x + u2.y * p2.y;
    float preneg  = u2.x * n2.x + u2.y * n2.y;
    float postpos = pux * ppx + puy * ppy;
    float postneg = pux * pnx + puy * pny;

#pragma unroll
    for (int o = 16; o; o >>= 1) {
        prepos  += __shfl_xor_sync(0xffffffffu, prepos, o);
        preneg  += __shfl_xor_sync(0xffffffffu, preneg, o);
        postpos += __shfl_xor_sync(0xffffffffu, postpos, o);
        postneg += __shfl_xor_sync(0xffffffffu, postneg, o);
    }
    if (lane == 0) {
        out[b]          = postpos * (1.f / (1.f + expf(-prepos)));
        out[Bn + b]     = postneg * (1.f / (1.f + expf(-preneg)));
        out[2 * Bn + b] = prepos;
        out[3 * Bn + b] = preneg;
    }
}

// ---------------------------------------------------------------------------
// Host launcher — kernel launches only, graph-capturable, allocation-free.
// ---------------------------------------------------------------------------
extern "C" void kernel_launch(void* const* d_in, const int* in_sizes, int n_in,
                              void* d_out, int out_size) {
    const float* v_feat   = (const float*)d_in[0];
    const float* a_feat   = (const float*)d_in[1];
    const float* word_emb = (const float*)d_in[2];
    const float* id_emb   = (const float*)d_in[3];
    const float* pref     = (const float*)d_in[4];
    const float* mlp_w    = (const float*)d_in[5];
    const float* mlp_b    = (const float*)d_in[6];
    const float* c1w      = (const float*)d_in[7];
    const float* l1w      = (const float*)d_in[8];
    const float* l1b      = (const float*)d_in[9];
    const float* g1w      = (const float*)d_in[10];
    const float* g1b      = (const float*)d_in[11];
    const float* c2w      = (const float*)d_in[12];
    const float* l2w      = (const float*)d_in[13];
    const float* l2b      = (const float*)d_in[14];
    const float* g2w      = (const float*)d_in[15];
    const float* g2b      = (const float*)d_in[16];
    const int*   edge     = (const int*)d_in[17];
    const int*   words    = (const int*)d_in[18];
    const int*   un       = (const int*)d_in[19];
    const int*   pn       = (const int*)d_in[20];
    const int*   nn       = (const int*)d_in[21];

    int E  = in_sizes[17] / 2;
    int W  = in_sizes[18] / 2;
    int Bn = in_sizes[19];
    const int* src = edge;
    const int* dst = edge + E;
    const int* item_ids = words;
    const int* word_ids = words + W;

    // ---- t_feat ----
    tfeat_kernel<<<I_, 128>>>(item_ids, word_ids, word_emb, W);

    // ---- CSR build (counting sort by dst) ----
    int nScanBlocks = (N_ + SCAN_B - 1) / SCAN_B;
    zero_int_kernel<<<(N_ + 255) / 256, 256>>>(N_);
    hist_kernel<<<(E + 255) / 256, 256>>>(dst, E);
    scan1_kernel<<<nScanBlocks, SCAN_B>>>(N_);
    scan2_kernel<<<1, SCAN_B>>>(nScanBlocks);
    scan3_kernel<<<(N_ + 255) / 256, 256>>>(N_, E);
    zero_int_kernel<<<(N_ + 255) / 256, 256>>>(N_);
    fill_kernel<<<(E + 255) / 256, 256>>>(src, dst, E);

    dim3 gN128((N_ + BM - 1) / BM, 2);   // N rows, 128 cols
    dim3 gN64((N_ + BM - 1) / BM, 1);    // N rows, 64 cols
    dim3 gI128((I_ + BM - 1) / BM, 2);   // I rows, 128 cols

    for (int m = 0; m < 3; m++) {
        const float* feat = (m == 0) ? v_feat : (m == 1) ? a_feat : nullptr;

        // MLP: x[U:] = feat @ mlp_w^T + mlp_b
        gemm_kernel<128, true, false, false><<<gI128, 256>>>(
            feat, OFF_TFEAT, mlp_w + (size_t)m * DL * DL, mlp_b + (size_t)m * DL,
            0, nullptr, OFF_X + (long long)U_ * DL, I_, DL);
        // normalize (copies pref rows in)
        normalize_kernel<<<(N_ + 7) / 8, 256>>>(pref + (size_t)m * U_ * DL);

        // ---- layer 1 ----
        gemm_kernel<128, false, false, false><<<gN128, 256>>>(
            nullptr, OFF_X, c1w + (size_t)m * DL * DL, nullptr,
            0, nullptr, OFF_Y, N_, DL);
        gather_kernel<128><<<(N_ * 4 + 7) / 8, 256>>>(OFF_Y, OFF_H);
        gemm_kernel<128, true, false, false><<<gN64, 256>>>(
            nullptr, OFF_X, l1w + (size_t)m * DX * DL, l1b + (size_t)m * DX,
            0, nullptr, OFF_T2, N_, DX);
        gemm_kernel<128, true, true, true><<<gN64, 256>>>(
            nullptr, OFF_H, g1w + (size_t)m * DX * DL, g1b + (size_t)m * DX,
            OFF_T2, id_emb, OFF_XS, N_, DX);

        // ---- layer 2 ----
        gemm_kernel<64, false, false, false><<<gN64, 256>>>(
            nullptr, OFF_XS, c2w + (size_t)m * DX * DX, nullptr,
            0, nullptr, OFF_Y, N_, DX);
        gather_kernel<64><<<(N_ * 2 + 7) / 8, 256>>>(OFF_Y, OFF_H);
        gemm_kernel<64, true, false, false><<<gN64, 256>>>(
            nullptr, OFF_XS, l2w + (size_t)m * DX * DX, l2b + (size_t)m * DX,
            0, nullptr, OFF_T2, N_, DX);
        gemm_kernel<64, true, true, true><<<gN64, 256>>>(
            nullptr, OFF_H, g2w + (size_t)m * DX * DX, g2b + (size_t)m * DX,
            OFF_T2, id_emb, OFF_REPS + (long long)m * N_ * DX, N_, DX);
    }

    score_kernel<<<(Bn + 7) / 8, 256>>>(un, pn, nn, (float*)d_out, Bn);
}